// round 8
// baseline (speedup 1.0000x reference)
#include <cuda_runtime.h>
#include <math.h>
#include <stdint.h>

#define BATCH 256
#define VOCAB 128000
#define NBINS 8192
#define CAP   4096
#define NEG_INF __int_as_float(0xff800000)
typedef unsigned long long ull;

// ---------------- scratch (device globals; no allocations allowed) ----------
__device__ float    g_histG[BATCH * NBINS];          // 8MB merged histograms
__device__ ull      g_cand[BATCH * CAP];             // boundary-bin candidates
__device__ int      g_ccount[BATCH];
__device__ unsigned g_rmk[BATCH];                    // okey(row max value)
__device__ unsigned g_amin[BATCH];                   // argmax (first occurrence)
__device__ ull      g_best[BATCH];                   // (okey(score)<<32)|~v
__device__ float    g_sk[BATCH];                     // kept mass (Ms-anchored)
__device__ int      g_Bstar[BATCH];                  // -2 = degenerate row
__device__ double   g_cumAbove[BATCH];
__device__ double   g_Z[BATCH];

// monotone float<->uint key (total order)
__device__ __forceinline__ unsigned okey(float f){
    unsigned b = __float_as_uint(f);
    return b ^ ((b & 0x80000000u) ? 0xFFFFFFFFu : 0x80000000u);
}
__device__ __forceinline__ float key_to_float(unsigned k){
    unsigned b = (k & 0x80000000u) ? (k ^ 0x80000000u) : ~k;
    return __uint_as_float(b);
}
__device__ __forceinline__ float ex2(float x){      // single MUFU.EX2
    float r; asm("ex2.approx.f32 %0, %1;" : "=f"(r) : "f"(x)); return r;
}

// jax threefry2x32-20, key = (0, 42) — scalar version (cold paths)
__device__ __forceinline__ void threefry(unsigned c0, unsigned c1,
                                         unsigned &o0, unsigned &o1){
    const unsigned k0 = 0u, k1 = 42u;
    const unsigned k2 = 0x1BD11BDAu ^ k0 ^ k1;
    unsigned x0 = c0 + k0, x1 = c1 + k1;
#define TFR(r) { x0 += x1; x1 = ((x1 << r) | (x1 >> (32 - r))); x1 ^= x0; }
    TFR(13) TFR(15) TFR(26) TFR(6)   x0 += k1; x1 += k2 + 1u;
    TFR(17) TFR(29) TFR(16) TFR(24)  x0 += k2; x1 += k0 + 2u;
    TFR(13) TFR(15) TFR(26) TFR(6)   x0 += k0; x1 += k1 + 3u;
    TFR(17) TFR(29) TFR(16) TFR(24)  x0 += k1; x1 += k2 + 4u;
    TFR(13) TFR(15) TFR(26) TFR(6)   x0 += k2; x1 += k0 + 5u;
#undef TFR
    o0 = x0; o1 = x1;
}
__device__ __forceinline__ unsigned jax_bits32(unsigned i){
    unsigned o0, o1; threefry(0u, i, o0, o1); return o0 ^ o1;
}

// 4 independent ciphers in lockstep (counters cbase..cbase+3, c0=0) — 4x ILP
__device__ __forceinline__ void threefry4(unsigned cbase, unsigned out[4]){
    const unsigned k0 = 0u, k1 = 42u;
    const unsigned k2 = 0x1BD11BDAu ^ k0 ^ k1;
    unsigned x0[4], x1[4];
#pragma unroll
    for (int q = 0; q < 4; q++){ x0[q] = k0; x1[q] = (cbase + q) + k1; }
#define QR(r) _Pragma("unroll") \
    for (int q = 0; q < 4; q++){ \
        x0[q] += x1[q]; \
        x1[q] = ((x1[q] << r) | (x1[q] >> (32 - r))) ^ x0[q]; \
    }
#define KI(a, b) _Pragma("unroll") \
    for (int q = 0; q < 4; q++){ x0[q] += (a); x1[q] += (b); }
    QR(13) QR(15) QR(26) QR(6)   KI(k1, k2 + 1u)
    QR(17) QR(29) QR(16) QR(24)  KI(k2, k0 + 2u)
    QR(13) QR(15) QR(26) QR(6)   KI(k0, k1 + 3u)
    QR(17) QR(29) QR(16) QR(24)  KI(k1, k2 + 4u)
    QR(13) QR(15) QR(26) QR(6)   KI(k2, k0 + 5u)
#undef QR
#undef KI
#pragma unroll
    for (int q = 0; q < 4; q++) out[q] = x0[q] ^ x1[q];
}

__device__ __forceinline__ float gumbel_from_bits(unsigned bits){
    float u = __uint_as_float((bits >> 9) | 0x3f800000u) - 1.0f;
    if (u <= 0.0f) u = 1.17549435e-38f;
    float inner = -log1pf(u - 1.0f);   // == -log(u) exactly
    return -logf(inner);
}
__device__ __forceinline__ float bin_top(unsigned bin){   // bin top-edge value
    return key_to_float((bin << 19) | 0x7FFFFu);
}

// ---------------- K0: init ---------------------------------------------------
__global__ void k0_init(){
    size_t id = (size_t)blockIdx.x * 1024 + threadIdx.x;
    float4* h4 = (float4*)g_histG;
    if (id < (size_t)BATCH * NBINS / 4) h4[id] = make_float4(0.f,0.f,0.f,0.f);
    if (id < BATCH){
        g_rmk[id] = 0u; g_amin[id] = 0xFFFFFFFFu;
        g_best[id] = 0ULL; g_sk[id] = 0.0f;
        g_ccount[id] = 0;
    }
}

// ---------------- K2a: raw-key weighted histogram + row max ------------------
__global__ void k2a_hist(const float* __restrict__ logits,
                         const float* __restrict__ temps){
    int row = blockIdx.y, part = blockIdx.x;        // 2 parts of 64000 elems
    __shared__ float bins[NBINS];                   // 32KB only
    __shared__ float sm[512];
    for (int i = threadIdx.x; i < NBINS; i += 512) bins[i] = 0.0f;
    __syncthreads();

    float t = temps[row]; float ts = (t == 0.0f) ? 1.0f : t;
    float c1 = __fdividef(1.4426950408889634f, ts);     // log2e / ts
    const float4* x4 = (const float4*)(logits + (size_t)row * VOCAB + part * 64000);
    float vmax = NEG_INF;
    for (int base = threadIdx.x; base < 16000; base += 2048){
        float4 f[4]; bool ok[4];
#pragma unroll
        for (int k = 0; k < 4; k++){
            int i = base + k * 512;
            ok[k] = (i < 16000);
            if (ok[k]) f[k] = x4[i];
        }
#pragma unroll
        for (int k = 0; k < 4; k++){
            if (!ok[k]) continue;
            float vals[4] = {f[k].x, f[k].y, f[k].z, f[k].w};
#pragma unroll
            for (int j = 0; j < 4; j++){
                float x = vals[j];
                vmax = fmaxf(vmax, x);
                unsigned bin = okey(x) >> 19;
                float d = x - bin_top(bin);         // exact (same binade)
                atomicAdd(&bins[bin], ex2(d * c1));
            }
        }
    }
    sm[threadIdx.x] = vmax; __syncthreads();
    for (int s = 256; s > 0; s >>= 1){
        if (threadIdx.x < s) sm[threadIdx.x] = fmaxf(sm[threadIdx.x], sm[threadIdx.x + s]);
        __syncthreads();
    }
    if (threadIdx.x == 0) atomicMax(&g_rmk[row], okey(sm[0]));
    float* gh = g_histG + (size_t)row * NBINS;
    for (int i = threadIdx.x; i < NBINS; i += 512)
        if (bins[i] != 0.0f) atomicAdd(&gh[i], bins[i]);
}

// ---------------- K2b: rescale + suffix scan -> boundary bin -----------------
__global__ void k2b_scan(const float* __restrict__ temps,
                         const float* __restrict__ topps){
    int row = blockIdx.x; int tid = threadIdx.x;   // 1024 threads
    __shared__ double sarr[1024];
    __shared__ int    sbi[1024];
    __shared__ double sZ;

    float t = temps[row]; float ts = (t == 0.0f) ? 1.0f : t;
    unsigned kmax = g_rmk[row];
    float xmax = key_to_float(kmax);
    double invd = 1.0 / (double)ts;

    const float4* gh4 = (const float4*)(g_histG + (size_t)row * NBINS);
    float4 h0 = gh4[tid * 2], h1 = gh4[tid * 2 + 1];
    float hv[8] = {h0.x, h0.y, h0.z, h0.w, h1.x, h1.y, h1.z, h1.w};

    int base = tid * 8;
    double mv[8]; double csum = 0.0;
#pragma unroll
    for (int j = 0; j < 8; j++){
        double m = 0.0;
        if (hv[j] > 0.0f){
            double arg = ((double)bin_top((unsigned)(base + j)) - (double)xmax) * invd;
            if (arg > -80.0) m = (double)hv[j] * exp(arg);  // gated f64 exp
        }
        mv[j] = m; csum += m;
    }
    sarr[tid] = csum; __syncthreads();
    for (int off = 1; off < 1024; off <<= 1){
        double v = sarr[tid];
        double a = (tid + off < 1024) ? sarr[tid + off] : 0.0;
        __syncthreads();
        sarr[tid] = v + a;
        __syncthreads();
    }
    double above = sarr[tid] - csum;
    if (tid == 0) sZ = sarr[0];
    __syncthreads();
    double Z = sZ;

    float p = fminf(fmaxf(topps[row], 0.0f), 1.0f);
    double pZ = (double)p * Z;

    int bestj = -1; double bestAbove = 0.0;
    double run = above;
    for (int j = 7; j >= 0; j--){
        double s = mv[j];
        if (run + s > pZ){ bestj = base + j; bestAbove = run; break; }
        run += s;
    }
    __syncthreads();
    sbi[tid] = bestj; sarr[tid] = bestAbove; __syncthreads();
    for (int s2 = 512; s2 > 0; s2 >>= 1){
        if (tid < s2 && sbi[tid + s2] > sbi[tid]){
            sbi[tid] = sbi[tid + s2];
            sarr[tid] = sarr[tid + s2];
        }
        __syncthreads();
    }
    if (tid == 0){
        int B = sbi[0];
        bool deg = (g_histG[(size_t)row * NBINS + (kmax >> 19)] == 0.0f) || (B < 0);
        if (deg){
            g_Bstar[row] = -2;          // keep only top max-bin element
            g_cumAbove[row] = 0.0;
            g_Z[row] = 0.0;
        } else {
            g_Bstar[row] = B;
            g_cumAbove[row] = sarr[0];
            g_Z[row] = Z;
        }
    }
}

// ---------------- K3: stream — gumbel over sure-keeps + gather candidates ----
__global__ void k3_stream(const float* __restrict__ logits,
                          const float* __restrict__ temps){
    int row = blockIdx.y;
    int B = g_Bstar[row];
    unsigned kmax = g_rmk[row];
    int Bstar = (B == -2) ? (int)(kmax >> 19) : B;
    float t = temps[row]; float ts = (t == 0.0f) ? 1.0f : t;
    float Ms = __fdiv_rn(key_to_float(kmax), ts);
    float xmaxv = key_to_float(kmax);
    // float thresholds (monotone with okey; data NaN-free)
    float candLo = key_to_float((unsigned)Bstar << 19);
    float keepLo = (Bstar >= 0x1FEF) ? __int_as_float(0x7f800000)
                                     : key_to_float((unsigned)(Bstar + 1) << 19);

    int base0 = blockIdx.x * 16000;                  // 8 chunks per row
    const float4* x4 = (const float4*)(logits + (size_t)row * VOCAB + base0);
    ull* candRow = g_cand + (size_t)row * CAP;
    unsigned iBase = (unsigned)row * (unsigned)VOCAB;

    float sk = 0.0f; ull bestp = 0ULL;
    for (int i0 = 0; i0 < 4000; i0 += 1024){
        float4 f[4]; bool ok[4];
#pragma unroll
        for (int k = 0; k < 4; k++){
            int i = i0 + threadIdx.x + k * 256;
            ok[k] = (i < 4000);
            if (ok[k]) f[k] = x4[i];
        }
#pragma unroll
        for (int k = 0; k < 4; k++){
            if (!ok[k]) continue;
            unsigned v0 = (unsigned)(base0 + (i0 + threadIdx.x + k * 256) * 4);
            float vals[4] = {f[k].x, f[k].y, f[k].z, f[k].w};
            bool kept[4];
#pragma unroll
            for (int j = 0; j < 4; j++){
                float x = vals[j];
                kept[j] = (x >= keepLo);
                // cold paths: boundary candidates + argmax ties
                if (!kept[j] && x >= candLo){
                    int pos = atomicAdd(&g_ccount[row], 1);
                    if (pos < CAP){
                        float s = __fdiv_rn(x, ts);
                        candRow[pos] = ((ull)okey(s) << 32) | (v0 + j);
                    }
                }
                if (x == xmaxv) atomicMin(&g_amin[row], v0 + j);
            }
            if (kept[0] | kept[1] | kept[2] | kept[3]){
                unsigned bits[4];
                threefry4(iBase + v0, bits);     // 4-wide ILP cipher
#pragma unroll
                for (int j = 0; j < 4; j++){
                    if (kept[j]){
                        float s = __fdiv_rn(vals[j], ts);
                        sk += __expf(s - Ms);
                        float sc = s + gumbel_from_bits(bits[j]);
                        ull p = ((ull)okey(sc) << 32) | (unsigned)(~(v0 + j));
                        if (p > bestp) bestp = p;
                    }
                }
            }
        }
    }

    __shared__ ull sp[256];
    __shared__ float sv[256];
    sp[threadIdx.x] = bestp; sv[threadIdx.x] = sk;
    __syncthreads();
    for (int s = 128; s > 0; s >>= 1){
        if (threadIdx.x < s){
            if (sp[threadIdx.x + s] > sp[threadIdx.x])
                sp[threadIdx.x] = sp[threadIdx.x + s];
            sv[threadIdx.x] += sv[threadIdx.x + s];
        }
        __syncthreads();
    }
    if (threadIdx.x == 0){
        if (sp[0] != 0ULL) atomicMax(&g_best[row], sp[0]);
        if (sv[0] != 0.0f) atomicAdd(&g_sk[row], sv[0]);
    }
}

// ---------------- K4: per-row finalize — sort cands, cut, sample, output -----
__global__ void k4_final(const float* __restrict__ logits,
                         const float* __restrict__ temps,
                         const float* __restrict__ topps,
                         float* __restrict__ out){
    int row = blockIdx.x;
    int B = g_Bstar[row];
    unsigned kmax = g_rmk[row];
    int Bstar = (B == -2) ? (int)(kmax >> 19) : B;
    __shared__ ull keys[CAP];                 // 32KB
    __shared__ double sarr[1024];
    __shared__ int sli[1024];
    __shared__ ull sC;

    float t = temps[row]; float ts = (t == 0.0f) ? 1.0f : t;
    float Ms = __fdiv_rn(key_to_float(kmax), ts);
    int count = min(g_ccount[row], CAP);
    unsigned iBase = (unsigned)row * (unsigned)VOCAB;

    if (count == 0){                          // guard; ~never (bin non-empty)
        if (threadIdx.x == 0)
            sC = ((ull)okey(__fdiv_rn(key_to_float((unsigned)Bstar << 19), ts)) << 32);
    } else {
        int n = 1; while (n < count) n <<= 1; if (n < 2) n = 2;
        for (int i = threadIdx.x; i < n; i += blockDim.x)
            keys[i] = (i < count) ? g_cand[(size_t)row * CAP + i] : 0ULL;
        __syncthreads();

        // bitonic sort DESCENDING on packed (okey(s), idx)
        for (int k2 = 2; k2 <= n; k2 <<= 1){
            for (int j = k2 >> 1; j > 0; j >>= 1){
                for (int i = threadIdx.x; i < n; i += blockDim.x){
                    int ixj = i ^ j;
                    if (ixj > i){
                        ull a = keys[i], b = keys[ixj];
                        bool seg = ((i & k2) == 0);
                        if (seg ? (a < b) : (a > b)){ keys[i] = b; keys[ixj] = a; }
                    }
                }
                __syncthreads();
            }
        }

        double pZ = (double)fminf(fmaxf(topps[row], 0.0f), 1.0f) * g_Z[row];
        double cumAbove = g_cumAbove[row];
        int m = (n + 1023) / 1024;   // <= 4
        int lo = threadIdx.x * m;
        double ev[4];
        double ls = 0.0;
        for (int q = 0; q < m; q++){
            int i = lo + q; double e = 0.0;
            if (i < count){
                double sv2 = (double)key_to_float((unsigned)(keys[i] >> 32));
                e = exp(sv2 - (double)Ms);
            }
            ev[q] = e; ls += e;
        }
        sarr[threadIdx.x] = ls; __syncthreads();
        for (int off = 1; off < 1024; off <<= 1){
            double v = sarr[threadIdx.x];
            double a = (threadIdx.x >= off) ? sarr[threadIdx.x - off] : 0.0;
            __syncthreads();
            sarr[threadIdx.x] = v + a;
            __syncthreads();
        }
        double run = sarr[threadIdx.x] - ls + cumAbove;
        int lastKept = -1;
        for (int q = 0; q < m; q++){
            int i = lo + q;
            run += ev[q];
            if (i < count && run <= pZ) lastKept = i;
        }
        sli[threadIdx.x] = lastKept; __syncthreads();
        for (int s2 = 512; s2 > 0; s2 >>= 1){
            if (threadIdx.x < s2)
                sli[threadIdx.x] = max(sli[threadIdx.x], sli[threadIdx.x + s2]);
            __syncthreads();
        }
        if (threadIdx.x == 0){
            int iL = sli[0];
            ull C;
            if (iL >= 0)                      C = keys[iL];
            else if (g_cumAbove[row] > 0.0){
                float xHi = key_to_float((unsigned)(Bstar + 1) << 19);
                C = ((ull)okey(__fdiv_rn(xHi, ts)) << 32);
            } else                            C = keys[0];  // keep top element
            sC = C;
        }
    }
    __syncthreads();
    ull C = sC;

    // candidate contributions (kept subset)
    float sk = 0.0f; ull bestp = 0ULL;
    for (int i = threadIdx.x; i < count; i += 1024){
        ull e = keys[i];                   // sorted copy still in smem
        if (e >= C){
            unsigned v = (unsigned)e;
            float s = key_to_float((unsigned)(e >> 32));
            sk += __expf(s - Ms);
            float sc = s + gumbel_from_bits(jax_bits32(iBase + v));
            ull p = ((ull)okey(sc) << 32) | (unsigned)(~v);
            if (p > bestp) bestp = p;
        }
    }
    __shared__ ull sp[1024];
    __shared__ float svf[1024];
    sp[threadIdx.x] = bestp; svf[threadIdx.x] = sk;
    __syncthreads();
    for (int s = 512; s > 0; s >>= 1){
        if (threadIdx.x < s){
            if (sp[threadIdx.x + s] > sp[threadIdx.x])
                sp[threadIdx.x] = sp[threadIdx.x + s];
            svf[threadIdx.x] += svf[threadIdx.x + s];
        }
        __syncthreads();
    }

    if (threadIdx.x == 0){
        ull bestAll = g_best[row];
        if (sp[0] > bestAll) bestAll = sp[0];
        float skAll = g_sk[row] + svf[0];
        unsigned greedy = g_amin[row];
        unsigned tok;
        if (t == 0.0f) tok = greedy;
        else {
            unsigned cand = ~(unsigned)(bestAll & 0xFFFFFFFFu);
            tok = (cand < (unsigned)VOCAB) ? cand : greedy;
        }
        float stok = __fdiv_rn(logits[(size_t)row * VOCAB + tok], ts);
        ull pT = ((ull)okey(stok) << 32) | tok;
        float sel = (pT >= C) ? stok : NEG_INF;
        float lp = (skAll > 0.0f) ? (sel - (Ms + logf(skAll))) : 0.0f;
        out[row]          = (float)tok;
        out[BATCH + row]  = lp;
    }
}

// ---------------- launch -----------------------------------------------------
extern "C" void kernel_launch(void* const* d_in, const int* in_sizes, int n_in,
                              void* d_out, int out_size){
    const float* logits = (const float*)d_in[0];
    const float* temps  = (const float*)d_in[1];
    const float* topps  = (const float*)d_in[2];
    float* out = (float*)d_out;

    k0_init  <<<512, 1024>>>();
    k2a_hist <<<dim3(2, BATCH), 512>>>(logits, temps);
    k2b_scan <<<BATCH, 1024>>>(temps, topps);
    k3_stream<<<dim3(8, BATCH), 256>>>(logits, temps);
    k4_final <<<BATCH, 1024>>>(logits, temps, topps, out);
}

// round 9
// speedup vs baseline: 1.5975x; 1.5975x over previous
#include <cuda_runtime.h>
#include <math.h>
#include <stdint.h>

#define BATCH 256
#define VOCAB 128000
#define CAP   4096
#define NEG_INF __int_as_float(0xff800000)
typedef unsigned long long ull;

// ---------------- scratch (device globals; no allocations allowed) ----------
__device__ float    g_l1[BATCH*32];     // level-1 bucket masses
__device__ float    g_l2[BATCH*32];     // level-2 bucket masses
__device__ ull      g_cand[BATCH*CAP];  // boundary-bucket candidates
__device__ int      g_ccount[BATCH];
__device__ unsigned g_rmk[BATCH];       // okey(row max value)
__device__ unsigned g_amin[BATCH];      // argmax (first occurrence)
__device__ ull      g_best[BATCH];      // (okey(score)<<32)|~v
__device__ int      g_B1[BATCH];        // level-1 boundary bucket
__device__ int      g_Qcut[BATCH];      // global sub-bucket index of boundary
__device__ double   g_cumA1[BATCH];     // mass strictly above bucket B1
__device__ double   g_cumA2[BATCH];     // mass strictly above final bucket
__device__ double   g_Z[BATCH];

// monotone float<->uint key (total order)
__device__ __forceinline__ unsigned okey(float f){
    unsigned b = __float_as_uint(f);
    return b ^ ((b & 0x80000000u) ? 0xFFFFFFFFu : 0x80000000u);
}
__device__ __forceinline__ float key_to_float(unsigned k){
    unsigned b = (k & 0x80000000u) ? (k ^ 0x80000000u) : ~k;
    return __uint_as_float(b);
}
__device__ __forceinline__ float ex2(float x){      // single MUFU.EX2
    float r; asm("ex2.approx.f32 %0, %1;" : "=f"(r) : "f"(x)); return r;
}

// bucket index machinery — IDENTICAL formula in every kernel:
//   u  = rn(xmax - x);  q = rn(u * cq),  cq = rn(1.28/ts)   (32 buckets / 25 ts)
//   qq = (int)rn(q*32)  (exact scale)  -> global sub-bucket in [0,1024)
// out-of-range (q >= 32) carries mass < V*e^-25 ~ 2e-6 rel: excluded everywhere.
__device__ __forceinline__ bool qindex(float x, float xmax, float cq, int &qq){
    float u = __fadd_rn(xmax, -x);
    float q = __fmul_rn(u, cq);
    if (q >= 32.0f) return false;
    qq = (int)__fmul_rn(q, 32.0f);
    return true;
}

// jax threefry2x32-20, key = (0, 42)
__device__ __forceinline__ void threefry(unsigned c0, unsigned c1,
                                         unsigned &o0, unsigned &o1){
    const unsigned k0 = 0u, k1 = 42u;
    const unsigned k2 = 0x1BD11BDAu ^ k0 ^ k1;
    unsigned x0 = c0 + k0, x1 = c1 + k1;
#define TFR(r) { x0 += x1; x1 = ((x1 << r) | (x1 >> (32 - r))); x1 ^= x0; }
    TFR(13) TFR(15) TFR(26) TFR(6)   x0 += k1; x1 += k2 + 1u;
    TFR(17) TFR(29) TFR(16) TFR(24)  x0 += k2; x1 += k0 + 2u;
    TFR(13) TFR(15) TFR(26) TFR(6)   x0 += k0; x1 += k1 + 3u;
    TFR(17) TFR(29) TFR(16) TFR(24)  x0 += k1; x1 += k2 + 4u;
    TFR(13) TFR(15) TFR(26) TFR(6)   x0 += k2; x1 += k0 + 5u;
#undef TFR
    o0 = x0; o1 = x1;
}
__device__ __forceinline__ unsigned jax_bits32(unsigned i){
    unsigned o0, o1; threefry(0u, i, o0, o1); return o0 ^ o1;
}
__device__ __forceinline__ float gumbel_from_bits(unsigned bits){
    float u = __uint_as_float((bits >> 9) | 0x3f800000u) - 1.0f;
    if (u <= 0.0f) u = 1.17549435e-38f;
    float inner = -log1pf(u - 1.0f);   // == -log(u) exactly
    return -logf(inner);
}

// ---------------- K0: init ---------------------------------------------------
__global__ void k_init(){
    int id = blockIdx.x * 1024 + threadIdx.x;
    if (id < BATCH*32){ g_l1[id] = 0.0f; g_l2[id] = 0.0f; }
    if (id < BATCH){
        g_rmk[id] = 0u; g_amin[id] = 0xFFFFFFFFu;
        g_best[id] = 0ULL; g_ccount[id] = 0;
    }
}

// ---------------- K1: row max -------------------------------------------------
__global__ void k_max(const float* __restrict__ logits){
    int row = blockIdx.y, part = blockIdx.x;      // 4 parts of 32000
    const float4* x4 = (const float4*)(logits + (size_t)row * VOCAB + part * 32000);
    float vmax = NEG_INF;
    for (int base = threadIdx.x; base < 8000; base += 2048){
        float4 f[4]; bool ok[4];
#pragma unroll
        for (int k = 0; k < 4; k++){
            int i = base + k * 512;
            ok[k] = (i < 8000);
            if (ok[k]) f[k] = x4[i];
        }
#pragma unroll
        for (int k = 0; k < 4; k++){
            if (!ok[k]) continue;
            vmax = fmaxf(vmax, fmaxf(fmaxf(f[k].x, f[k].y), fmaxf(f[k].z, f[k].w)));
        }
    }
    __shared__ float sm[512];
    sm[threadIdx.x] = vmax; __syncthreads();
    for (int s = 256; s > 0; s >>= 1){
        if (threadIdx.x < s) sm[threadIdx.x] = fmaxf(sm[threadIdx.x], sm[threadIdx.x + s]);
        __syncthreads();
    }
    if (threadIdx.x == 0) atomicMax(&g_rmk[row], okey(sm[0]));
}

// ---------------- K2: level-1 histogram (private smem slots, NO atomics) -----
__global__ void k_h1(const float* __restrict__ logits,
                     const float* __restrict__ temps){
    int row = blockIdx.y, part = blockIdx.x;      // 8 parts of 16000
    __shared__ float hist[32*256];                // slot = bucket*256+tid
    int tid = threadIdx.x;
    for (int i = tid; i < 8192; i += 256) hist[i] = 0.0f;
    __syncthreads();

    float t = temps[row]; float ts = (t == 0.0f) ? 1.0f : t;
    float xmax = key_to_float(g_rmk[row]);
    float cq  = __fdiv_rn(1.28f, ts);
    float c1n = __fdiv_rn(-1.4426950408889634f, ts);   // -log2e/ts
    const float4* x4 = (const float4*)(logits + (size_t)row * VOCAB + part * 16000);

    for (int base = tid; base < 4000; base += 1024){
        float4 f[4]; bool ok[4];
#pragma unroll
        for (int k = 0; k < 4; k++){
            int i = base + k * 256;
            ok[k] = (i < 4000);
            if (ok[k]) f[k] = x4[i];
        }
#pragma unroll
        for (int k = 0; k < 4; k++){
            if (!ok[k]) continue;
            float vals[4] = {f[k].x, f[k].y, f[k].z, f[k].w};
#pragma unroll
            for (int j = 0; j < 4; j++){
                float x = vals[j];
                int qq;
                if (qindex(x, xmax, cq, qq)){
                    float w = ex2(__fmul_rn(__fadd_rn(xmax, -x), c1n));
                    hist[(qq >> 5) * 256 + tid] += w;
                }
            }
        }
    }
    __syncthreads();
    // merge: thread = (bucket bk, group g); sum 32 thread-slots, offset by lane
    int bk = tid & 31, g = tid >> 5, lane = tid & 31;
    float part_sum = 0.0f;
#pragma unroll
    for (int k = 0; k < 32; k++){
        int idx = g * 32 + ((k + lane) & 31);
        part_sum += hist[bk * 256 + idx];
    }
    if (part_sum != 0.0f) atomicAdd(&g_l1[row * 32 + bk], part_sum);
}

// ---------------- K3: level-1 scan -> boundary bucket B1 ---------------------
__global__ void k_s1(const float* __restrict__ temps,
                     const float* __restrict__ topps){
    int row = blockIdx.x; int lane = threadIdx.x;   // 32 threads
    double m = (double)g_l1[row * 32 + lane];
    double Z = m;
    for (int o = 16; o > 0; o >>= 1) Z += __shfl_xor_sync(0xFFFFFFFFu, Z, o);
    float p = fminf(fmaxf(topps[row], 0.0f), 1.0f);
    double pZ = (double)p * Z;
    double run = 0.0, cA = 0.0; int B = -1;
    for (int b = 0; b < 32; b++){
        double mb = __shfl_sync(0xFFFFFFFFu, m, b);
        if (B < 0 && run + mb > pZ){ B = b; cA = run; }
        if (B < 0) run += mb;
    }
    if (B < 0){ B = 31; cA = run - __shfl_sync(0xFFFFFFFFu, m, 31); }
    if (lane == 0){ g_B1[row] = B; g_cumA1[row] = cA; g_Z[row] = Z; }
}

// ---------------- K4: level-2 histogram (gated on B1) ------------------------
__global__ void k_h2(const float* __restrict__ logits,
                     const float* __restrict__ temps){
    int row = blockIdx.y, part = blockIdx.x;
    __shared__ float hist[32*256];
    int tid = threadIdx.x;
    for (int i = tid; i < 8192; i += 256) hist[i] = 0.0f;
    __syncthreads();

    float t = temps[row]; float ts = (t == 0.0f) ? 1.0f : t;
    float xmax = key_to_float(g_rmk[row]);
    int B1 = g_B1[row];
    float cq  = __fdiv_rn(1.28f, ts);
    float c1n = __fdiv_rn(-1.4426950408889634f, ts);
    const float4* x4 = (const float4*)(logits + (size_t)row * VOCAB + part * 16000);

    for (int base = tid; base < 4000; base += 1024){
        float4 f[4]; bool ok[4];
#pragma unroll
        for (int k = 0; k < 4; k++){
            int i = base + k * 256;
            ok[k] = (i < 4000);
            if (ok[k]) f[k] = x4[i];
        }
#pragma unroll
        for (int k = 0; k < 4; k++){
            if (!ok[k]) continue;
            float vals[4] = {f[k].x, f[k].y, f[k].z, f[k].w};
#pragma unroll
            for (int j = 0; j < 4; j++){
                float x = vals[j];
                int qq;
                if (qindex(x, xmax, cq, qq) && (qq >> 5) == B1){
                    float w = ex2(__fmul_rn(__fadd_rn(xmax, -x), c1n));
                    hist[(qq & 31) * 256 + tid] += w;
                }
            }
        }
    }
    __syncthreads();
    int bk = tid & 31, g = tid >> 5, lane = tid & 31;
    float part_sum = 0.0f;
#pragma unroll
    for (int k = 0; k < 32; k++){
        int idx = g * 32 + ((k + lane) & 31);
        part_sum += hist[bk * 256 + idx];
    }
    if (part_sum != 0.0f) atomicAdd(&g_l2[row * 32 + bk], part_sum);
}

// ---------------- K5: level-2 scan -> final cut bucket -----------------------
__global__ void k_s2(const float* __restrict__ temps,
                     const float* __restrict__ topps){
    int row = blockIdx.x; int lane = threadIdx.x;
    double m = (double)g_l2[row * 32 + lane];
    double Z = g_Z[row];
    float p = fminf(fmaxf(topps[row], 0.0f), 1.0f);
    double pZ = (double)p * Z;
    double run = g_cumA1[row], cA = run; int B = -1;
    for (int b = 0; b < 32; b++){
        double mb = __shfl_sync(0xFFFFFFFFu, m, b);
        if (B < 0 && run + mb > pZ){ B = b; cA = run; }
        if (B < 0) run += mb;
    }
    if (B < 0){ B = 31; cA = run - __shfl_sync(0xFFFFFFFFu, m, 31); }
    if (lane == 0){
        g_Qcut[row] = g_B1[row] * 32 + B;
        g_cumA2[row] = cA;
    }
}

// ---------------- K6: stream — compact keeps, dense gumbel, gather cands -----
__global__ void k_stream(const float* __restrict__ logits,
                         const float* __restrict__ temps){
    int row = blockIdx.y;
    int tid = threadIdx.x, warp = tid >> 5, lane = tid & 31;
    unsigned lmask = (1u << lane) - 1u;
    float t = temps[row]; float ts = (t == 0.0f) ? 1.0f : t;
    unsigned kmax = g_rmk[row];
    float xmaxv = key_to_float(kmax);
    float cq = __fdiv_rn(1.28f, ts);
    int Qcut = g_Qcut[row];
    int base0 = blockIdx.x * 16000;                 // element offset in row
    const float4* x4 = (const float4*)(logits + (size_t)row * VOCAB + base0);
    ull* candRow = g_cand + (size_t)row * CAP;
    unsigned iBase = (unsigned)row * (unsigned)VOCAB;

    __shared__ ull sbuf[8 * 256];                   // 16KB warp-private
    int wb = warp * 256;
    ull bestp = 0ULL;

    for (int t0 = 0; t0 < 4000; t0 += 512){         // 8 tiles, uniform bounds
        float xs[8]; bool kept[8];
#pragma unroll
        for (int k = 0; k < 2; k++){
            int i = t0 + tid + k * 256;
            float4 f = (i < 4000) ? x4[i]
                                  : make_float4(NEG_INF, NEG_INF, NEG_INF, NEG_INF);
            xs[k*4+0] = f.x; xs[k*4+1] = f.y; xs[k*4+2] = f.z; xs[k*4+3] = f.w;
        }
#pragma unroll
        for (int e = 0; e < 8; e++){
            int k = e >> 2, j = e & 3;
            int i = t0 + tid + k * 256;
            bool valid = (i < 4000);
            float x = xs[e];
            unsigned v = (unsigned)(base0 + i * 4 + j);
            kept[e] = false;
            int qq;
            if (valid && qindex(x, xmaxv, cq, qq)){
                if (qq < Qcut) kept[e] = true;
                else if (qq == Qcut){
                    int pos = atomicAdd(&g_ccount[row], 1);
                    if (pos < CAP){
                        float s = __fdiv_rn(x, ts);
                        candRow[pos] = ((ull)okey(s) << 32) | v;
                    }
                }
            }
            if (valid && x == xmaxv) atomicMin(&g_amin[row], v);
        }
        // warp compaction (no atomics, warp-synchronous)
        unsigned cnt = 0;
#pragma unroll
        for (int e = 0; e < 8; e++){
            int k = e >> 2, j = e & 3;
            unsigned bal = __ballot_sync(0xFFFFFFFFu, kept[e]);
            if (kept[e]){
                int i = t0 + tid + k * 256;
                unsigned v = (unsigned)(base0 + i * 4 + j);
                sbuf[wb + cnt + __popc(bal & lmask)] =
                    ((ull)__float_as_uint(xs[e]) << 32) | v;
            }
            cnt += __popc(bal);
        }
        // dense gumbel over compacted keeps (all lanes useful)
        for (unsigned i = lane; i < cnt; i += 32){
            ull e = sbuf[wb + i];
            unsigned v = (unsigned)e;
            float x = __uint_as_float((unsigned)(e >> 32));
            float s = __fdiv_rn(x, ts);
            float sc = s + gumbel_from_bits(jax_bits32(iBase + v));
            ull p = ((ull)okey(sc) << 32) | (unsigned)(~v);
            if (p > bestp) bestp = p;
        }
    }
    // warp-reduce best, merge
    for (int o = 16; o > 0; o >>= 1){
        ull other = __shfl_xor_sync(0xFFFFFFFFu, bestp, o);
        if (other > bestp) bestp = other;
    }
    if (lane == 0 && bestp != 0ULL) atomicMax(&g_best[row], bestp);
}

// ---------------- K7: per-row finalize — sort cands, cut, sample, output -----
__global__ void k_final(const float* __restrict__ logits,
                        const float* __restrict__ temps,
                        const float* __restrict__ topps,
                        float* __restrict__ out){
    int row = blockIdx.x;
    __shared__ ull keys[CAP];                 // 32KB
    __shared__ double sarr[1024];
    __shared__ int sli[1024];
    __shared__ ull sC;

    float t = temps[row]; float ts = (t == 0.0f) ? 1.0f : t;
    unsigned kmax = g_rmk[row];
    float xmaxv = key_to_float(kmax);
    float Ms = __fdiv_rn(xmaxv, ts);
    float cq = __fdiv_rn(1.28f, ts);
    int Qcut = g_Qcut[row];
    double cumAbove = g_cumA2[row];
    int count = min(g_ccount[row], CAP);
    unsigned iBase = (unsigned)row * (unsigned)VOCAB;

    if (count == 0){                          // guard; ~never (bucket has mass)
        if (threadIdx.x == 0) sC = 0ULL;
    } else {
        int n = 1; while (n < count) n <<= 1; if (n < 2) n = 2;
        for (int i = threadIdx.x; i < n; i += blockDim.x)
            keys[i] = (i < count) ? g_cand[(size_t)row * CAP + i] : 0ULL;
        __syncthreads();

        // bitonic sort DESCENDING on packed (okey(s), idx)
        for (int k2 = 2; k2 <= n; k2 <<= 1){
            for (int j = k2 >> 1; j > 0; j >>= 1){
                for (int i = threadIdx.x; i < n; i += blockDim.x){
                    int ixj = i ^ j;
                    if (ixj > i){
                        ull a = keys[i], b = keys[ixj];
                        bool seg = ((i & k2) == 0);
                        if (seg ? (a < b) : (a > b)){ keys[i] = b; keys[ixj] = a; }
                    }
                }
                __syncthreads();
            }
        }

        double pZ = (double)fminf(fmaxf(topps[row], 0.0f), 1.0f) * g_Z[row];
        int m = (n + 1023) / 1024;   // <= 4
        int lo = threadIdx.x * m;
        double ev[4];
        double ls = 0.0;
        for (int q = 0; q < m; q++){
            int i = lo + q; double e = 0.0;
            if (i < count){
                double sv2 = (double)key_to_float((unsigned)(keys[i] >> 32));
                e = exp(sv2 - (double)Ms);
            }
            ev[q] = e; ls += e;
        }
        sarr[threadIdx.x] = ls; __syncthreads();
        for (int off = 1; off < 1024; off <<= 1){
            double v = sarr[threadIdx.x];
            double a = (threadIdx.x >= off) ? sarr[threadIdx.x - off] : 0.0;
            __syncthreads();
            sarr[threadIdx.x] = v + a;
            __syncthreads();
        }
        double run = sarr[threadIdx.x] - ls + cumAbove;
        int lastKept = -1;
        for (int q = 0; q < m; q++){
            int i = lo + q;
            run += ev[q];
            if (i < count && run <= pZ) lastKept = i;
        }
        sli[threadIdx.x] = lastKept; __syncthreads();
        for (int s2 = 512; s2 > 0; s2 >>= 1){
            if (threadIdx.x < s2)
                sli[threadIdx.x] = max(sli[threadIdx.x], sli[threadIdx.x + s2]);
            __syncthreads();
        }
        if (threadIdx.x == 0){
            int iL = sli[0];
            ull C;
            if (iL >= 0)             C = keys[iL];
            else if (cumAbove > 0.0) C = keys[0] + 1ULL;   // cut above all cands
            else                     C = keys[0];          // force-keep top
            sC = C;
        }
    }
    __syncthreads();
    ull C = sC;

    // candidate contributions (kept subset)
    float sk = 0.0f; ull bestp = 0ULL;
    for (int i = threadIdx.x; i < count; i += 1024){
        ull e = keys[i];
        if (e >= C){
            unsigned v = (unsigned)e;
            float s = key_to_float((unsigned)(e >> 32));
            sk += __expf(s - Ms);
            float sc = s + gumbel_from_bits(jax_bits32(iBase + v));
            ull p = ((ull)okey(sc) << 32) | (unsigned)(~v);
            if (p > bestp) bestp = p;
        }
    }
    __shared__ ull sp[1024];
    __shared__ float svf[1024];
    sp[threadIdx.x] = bestp; svf[threadIdx.x] = sk;
    __syncthreads();
    for (int s = 512; s > 0; s >>= 1){
        if (threadIdx.x < s){
            if (sp[threadIdx.x + s] > sp[threadIdx.x])
                sp[threadIdx.x] = sp[threadIdx.x + s];
            svf[threadIdx.x] += svf[threadIdx.x + s];
        }
        __syncthreads();
    }

    if (threadIdx.x == 0){
        ull bestAll = g_best[row];
        if (sp[0] > bestAll) bestAll = sp[0];
        double skAll = cumAbove + (double)svf[0];
        unsigned greedy = g_amin[row];
        unsigned tok;
        if (t == 0.0f) tok = greedy;
        else {
            unsigned cand = ~(unsigned)(bestAll & 0xFFFFFFFFu);
            tok = (cand < (unsigned)VOCAB) ? cand : greedy;
        }
        float xtok = logits[(size_t)row * VOCAB + tok];
        float stok = __fdiv_rn(xtok, ts);
        // kept check: sure-keep bucket OR >= candidate cut
        int qq; bool sure = qindex(xtok, xmaxv, cq, qq) && (qq < Qcut);
        ull pT = ((ull)okey(stok) << 32) | tok;
        float sel = (sure || pT >= C) ? stok : NEG_INF;
        double lz = (double)Ms + log(skAll);
        out[row]          = (float)tok;
        out[BATCH + row]  = (float)((double)sel - lz);
    }
}

// ---------------- launch -----------------------------------------------------
extern "C" void kernel_launch(void* const* d_in, const int* in_sizes, int n_in,
                              void* d_out, int out_size){
    const float* logits = (const float*)d_in[0];
    const float* temps  = (const float*)d_in[1];
    const float* topps  = (const float*)d_in[2];
    float* out = (float*)d_out;

    k_init  <<<16, 1024>>>();
    k_max   <<<dim3(4, BATCH), 512>>>(logits);
    k_h1    <<<dim3(8, BATCH), 256>>>(logits, temps);
    k_s1    <<<BATCH, 32>>>(temps, topps);
    k_h2    <<<dim3(8, BATCH), 256>>>(logits, temps);
    k_s2    <<<BATCH, 32>>>(temps, topps);
    k_stream<<<dim3(8, BATCH), 256>>>(logits, temps);
    k_final <<<BATCH, 1024>>>(logits, temps, topps, out);
}